// round 4
// baseline (speedup 1.0000x reference)
#include <cuda_runtime.h>
#include <math.h>

// Problem constants
static constexpr int Bsz  = 2;
static constexpr int Tlen = 2048;
static constexpr int Cdim = 1024;
static constexpr int H    = 16;
static constexpr int D    = 64;
static constexpr int M    = Bsz * Tlen;       // 4096 rows
static constexpr float RMS_EPS = 1.1920928955078125e-07f;

// Scratch (no allocation allowed): 4 x 16 MiB
__device__ float g_q[M * Cdim];
__device__ float g_k[M * Cdim];
__device__ float g_v[M * Cdim];
__device__ float g_y[M * Cdim];

// ---------------------------------------------------------------------------
// GEMM: Cout[M,1024] = A[M,1024] @ W[1024,1024]^T   (A,W row-major, K-major)
// 128x128 block tile, 16-deep K tile, 256 threads, 8x8 per thread (split 4+4)
// Double-buffered smem (one BAR per K-tile, global prefetch overlapped).
// ---------------------------------------------------------------------------
__device__ __forceinline__ void gemm_body(const float* __restrict__ A,
                                          const float* __restrict__ W,
                                          float* __restrict__ Cout)
{
    constexpr int K = 1024, N = 1024;
    constexpr int NT = K / 16;   // 64 K-tiles
    __shared__ float As[2][16][132];
    __shared__ float Ws[2][16][132];

    const int tid = threadIdx.x;
    const int tx  = tid & 15;
    const int ty  = tid >> 4;
    const int m0  = blockIdx.y * 128;
    const int n0  = blockIdx.x * 128;

    const int lr = tid >> 2;        // 0..63
    const int lc = (tid & 3) << 2;  // 0,4,8,12

    float acc[8][8];
#pragma unroll
    for (int i = 0; i < 8; i++)
#pragma unroll
        for (int j = 0; j < 8; j++) acc[i][j] = 0.0f;

    const float* Ap0 = A + (size_t)(m0 + lr) * K + lc;
    const float* Ap1 = Ap0 + (size_t)64 * K;
    const float* Wp0 = W + (size_t)(n0 + lr) * K + lc;
    const float* Wp1 = Wp0 + (size_t)64 * K;

    // Preload tile 0 into buffer 0
    {
        float4 a0 = *(const float4*)(Ap0);
        float4 a1 = *(const float4*)(Ap1);
        float4 w0 = *(const float4*)(Wp0);
        float4 w1 = *(const float4*)(Wp1);
        As[0][lc + 0][lr] = a0.x; As[0][lc + 1][lr] = a0.y;
        As[0][lc + 2][lr] = a0.z; As[0][lc + 3][lr] = a0.w;
        As[0][lc + 0][lr + 64] = a1.x; As[0][lc + 1][lr + 64] = a1.y;
        As[0][lc + 2][lr + 64] = a1.z; As[0][lc + 3][lr + 64] = a1.w;
        Ws[0][lc + 0][lr] = w0.x; Ws[0][lc + 1][lr] = w0.y;
        Ws[0][lc + 2][lr] = w0.z; Ws[0][lc + 3][lr] = w0.w;
        Ws[0][lc + 0][lr + 64] = w1.x; Ws[0][lc + 1][lr + 64] = w1.y;
        Ws[0][lc + 2][lr + 64] = w1.z; Ws[0][lc + 3][lr + 64] = w1.w;
    }
    __syncthreads();

    for (int it = 0; it < NT; it++) {
        const int cur = it & 1;
        const int nxt = cur ^ 1;

        float4 a0, a1, w0, w1;
        const bool has_next = (it + 1 < NT);
        if (has_next) {
            const int kn = (it + 1) * 16;
            a0 = *(const float4*)(Ap0 + kn);
            a1 = *(const float4*)(Ap1 + kn);
            w0 = *(const float4*)(Wp0 + kn);
            w1 = *(const float4*)(Wp1 + kn);
        }

#pragma unroll
        for (int kk = 0; kk < 16; kk++) {
            float4 a_0 = *(const float4*)&As[cur][kk][ty * 4];
            float4 a_1 = *(const float4*)&As[cur][kk][64 + ty * 4];
            float4 b_0 = *(const float4*)&Ws[cur][kk][tx * 4];
            float4 b_1 = *(const float4*)&Ws[cur][kk][64 + tx * 4];
            float av[8] = {a_0.x, a_0.y, a_0.z, a_0.w, a_1.x, a_1.y, a_1.z, a_1.w};
            float bv[8] = {b_0.x, b_0.y, b_0.z, b_0.w, b_1.x, b_1.y, b_1.z, b_1.w};
#pragma unroll
            for (int i = 0; i < 8; i++)
#pragma unroll
                for (int j = 0; j < 8; j++)
                    acc[i][j] = fmaf(av[i], bv[j], acc[i][j]);
        }

        if (has_next) {
            As[nxt][lc + 0][lr] = a0.x; As[nxt][lc + 1][lr] = a0.y;
            As[nxt][lc + 2][lr] = a0.z; As[nxt][lc + 3][lr] = a0.w;
            As[nxt][lc + 0][lr + 64] = a1.x; As[nxt][lc + 1][lr + 64] = a1.y;
            As[nxt][lc + 2][lr + 64] = a1.z; As[nxt][lc + 3][lr + 64] = a1.w;
            Ws[nxt][lc + 0][lr] = w0.x; Ws[nxt][lc + 1][lr] = w0.y;
            Ws[nxt][lc + 2][lr] = w0.z; Ws[nxt][lc + 3][lr] = w0.w;
            Ws[nxt][lc + 0][lr + 64] = w1.x; Ws[nxt][lc + 1][lr + 64] = w1.y;
            Ws[nxt][lc + 2][lr + 64] = w1.z; Ws[nxt][lc + 3][lr + 64] = w1.w;
            __syncthreads();
        }
    }

#pragma unroll
    for (int i = 0; i < 8; i++) {
        int row = m0 + ((i < 4) ? (ty * 4 + i) : (64 + ty * 4 + (i - 4)));
        float* cp = Cout + (size_t)row * N + n0;
        *(float4*)(cp + tx * 4)      = make_float4(acc[i][0], acc[i][1], acc[i][2], acc[i][3]);
        *(float4*)(cp + 64 + tx * 4) = make_float4(acc[i][4], acc[i][5], acc[i][6], acc[i][7]);
    }
}

__global__ void __launch_bounds__(256, 2) qkv_gemm_kernel(const float* __restrict__ x,
                                                          const float* __restrict__ wq,
                                                          const float* __restrict__ wk,
                                                          const float* __restrict__ wv)
{
    const float* W = (blockIdx.z == 0) ? wq : (blockIdx.z == 1) ? wk : wv;
    float* out     = (blockIdx.z == 0) ? g_q : (blockIdx.z == 1) ? g_k : g_v;
    gemm_body(x, W, out);
}

__global__ void __launch_bounds__(256, 2) proj_gemm_kernel(const float* __restrict__ wproj,
                                                           float* __restrict__ out)
{
    gemm_body(g_y, wproj, out);
}

// ---------------------------------------------------------------------------
// RMSNorm + RoPE, in-place on g_q and g_k. One warp per (b,t,h) head vector.
// Lane i owns the pair (d=i, d=i+32).
// ---------------------------------------------------------------------------
__global__ void __launch_bounds__(256) rope_kernel()
{
    const int warp = blockIdx.x * 8 + (threadIdx.x >> 5);
    const int lane = threadIdx.x & 31;
    const int NV   = M * H;  // vectors per tensor

    float* buf = (warp < NV) ? g_q : g_k;
    const int v = (warp < NV) ? warp : warp - NV;

    const int row = v >> 4;          // b*T + t
    const int h   = v & 15;
    const int t   = row & (Tlen - 1);

    float* p = buf + (size_t)row * Cdim + h * D;
    float x1 = p[lane];
    float x2 = p[lane + 32];

    float ss = x1 * x1 + x2 * x2;
#pragma unroll
    for (int m = 16; m > 0; m >>= 1)
        ss += __shfl_xor_sync(0xffffffffu, ss, m);

    const float r = rsqrtf(ss * (1.0f / 64.0f) + RMS_EPS);

    // inv_freq = 10000^(-lane/32) = 2^(-lane * log2(10000)/32)
    const float LOG2_BASE_OVER_32 = 0.41524101186092029f;  // log2(10000)/32
    const float inv_freq = exp2f(-(float)lane * LOG2_BASE_OVER_32);
    const float ang = (float)t * inv_freq;
    // Accurate sincos: angles reach ~2048 rad; fast __sincosf range reduction
    // would inject ~1e-3 absolute error. Keep the precise path.
    float s, c;
    sincosf(ang, &s, &c);

    const float n1 = x1 * r;
    const float n2 = x2 * r;
    p[lane]      = n1 * c + n2 * s;
    p[lane + 32] = n2 * c - n1 * s;
}

// ---------------------------------------------------------------------------
// Causal flash attention, fp32. Block = 64 queries of one (b,h).
// 256 threads as 16x16; each thread owns a 4x4 patch of the 64x64 tile.
// blockIdx.x is REVERSED onto q-blocks so heavy (long-history) CTAs launch
// first: better tail packing across the 148-SM chip.
// __launch_bounds__(256,2) caps regs at 128 to guarantee 2 CTAs/SM — the
// latency-hiding model depends on cross-CTA coverage of the K/V loads.
// Shared: Qs[64][68], Kst[64(d)][68(c)] (transposed K), Vs[64][68], Ps[64][68]
// ---------------------------------------------------------------------------
__global__ void __launch_bounds__(256, 2) attn_kernel()
{
    extern __shared__ float sm[];
    float (*Qs)[68]  = (float(*)[68])(sm);
    float (*Kst)[68] = (float(*)[68])(sm + 64 * 68);
    float (*Vs)[68]  = (float(*)[68])(sm + 2 * 64 * 68);
    float (*Ps)[68]  = (float(*)[68])(sm + 3 * 64 * 68);

    const int tid = threadIdx.x;
    const int tx  = tid & 15;
    const int ty  = tid >> 4;
    const int qb  = (gridDim.x - 1 - blockIdx.x);   // heavy blocks first
    const int q0  = qb * 64;
    const int bh  = blockIdx.y;
    const int b   = bh >> 4;
    const int h   = bh & 15;

    const float* Qg = g_q + ((size_t)(b * Tlen + q0)) * Cdim + h * D;

    // Load Q tile (row-major)
    {
        const int r  = tid >> 2;
        const int dc = (tid & 3) * 16;
#pragma unroll
        for (int i = 0; i < 4; i++) {
            float4 qv = *(const float4*)(Qg + (size_t)r * Cdim + dc + 4 * i);
            *(float4*)&Qs[r][dc + 4 * i] = qv;
        }
    }

    float m_i[4], l_i[4], o[4][4];
#pragma unroll
    for (int i = 0; i < 4; i++) {
        m_i[i] = -INFINITY;
        l_i[i] = 0.0f;
#pragma unroll
        for (int j = 0; j < 4; j++) o[i][j] = 0.0f;
    }
    __syncthreads();

    const int ntiles = qb + 1;
    const float scale = 0.125f;  // 1/sqrt(64)

    for (int kt = 0; kt < ntiles; kt++) {
        const int k0 = kt * 64;
        __syncthreads();  // prior stage-2 done with Vs/Ps

        // Load K (transposed into Kst[d][c]) and V (row-major)
        {
            const float* Kg = g_k + ((size_t)(b * Tlen + k0)) * Cdim + h * D;
            const float* Vg = g_v + ((size_t)(b * Tlen + k0)) * Cdim + h * D;
            const int c  = tid >> 4;         // 0..15
            const int dd = (tid & 15) * 4;   // 0..60
#pragma unroll
            for (int ii = 0; ii < 4; ii++) {
                const int cc = c + ii * 16;
                float4 kv = *(const float4*)(Kg + (size_t)cc * Cdim + dd);
                Kst[dd + 0][cc] = kv.x; Kst[dd + 1][cc] = kv.y;
                Kst[dd + 2][cc] = kv.z; Kst[dd + 3][cc] = kv.w;
                float4 vv = *(const float4*)(Vg + (size_t)cc * Cdim + dd);
                *(float4*)&Vs[cc][dd] = vv;
            }
        }
        __syncthreads();

        // S = Q K^T (per-thread 4x4)
        float s[4][4];
#pragma unroll
        for (int i = 0; i < 4; i++)
#pragma unroll
            for (int j = 0; j < 4; j++) s[i][j] = 0.0f;

#pragma unroll
        for (int d = 0; d < 64; d += 4) {
            float4 qa[4], kb[4];
#pragma unroll
            for (int i = 0; i < 4; i++) qa[i] = *(const float4*)&Qs[ty * 4 + i][d];
#pragma unroll
            for (int dd = 0; dd < 4; dd++) kb[dd] = *(const float4*)&Kst[d + dd][tx * 4];
#pragma unroll
            for (int i = 0; i < 4; i++) {
                const float* qp = (const float*)&qa[i];
#pragma unroll
                for (int j = 0; j < 4; j++) {
                    float acc = s[i][j];
                    acc = fmaf(qp[0], ((const float*)&kb[0])[j], acc);
                    acc = fmaf(qp[1], ((const float*)&kb[1])[j], acc);
                    acc = fmaf(qp[2], ((const float*)&kb[2])[j], acc);
                    acc = fmaf(qp[3], ((const float*)&kb[3])[j], acc);
                    s[i][j] = acc;
                }
            }
        }

        const bool diag = (k0 == q0);
#pragma unroll
        for (int i = 0; i < 4; i++)
#pragma unroll
            for (int j = 0; j < 4; j++) {
                float v = s[i][j] * scale;
                if (diag && (tx * 4 + j > ty * 4 + i)) v = -INFINITY;
                s[i][j] = v;
            }

        // Online softmax per row; rows of this thread live in a 16-lane group
#pragma unroll
        for (int i = 0; i < 4; i++) {
            float mx = fmaxf(fmaxf(s[i][0], s[i][1]), fmaxf(s[i][2], s[i][3]));
#pragma unroll
            for (int mm = 8; mm > 0; mm >>= 1)
                mx = fmaxf(mx, __shfl_xor_sync(0xffffffffu, mx, mm));
            const float mnew  = fmaxf(m_i[i], mx);
            const float alpha = __expf(m_i[i] - mnew);
            m_i[i] = mnew;

            float rs = 0.0f;
#pragma unroll
            for (int j = 0; j < 4; j++) {
                float p = __expf(s[i][j] - mnew);
                s[i][j] = p;
                rs += p;
            }
#pragma unroll
            for (int mm = 8; mm > 0; mm >>= 1)
                rs += __shfl_xor_sync(0xffffffffu, rs, mm);

            l_i[i] = l_i[i] * alpha + rs;
#pragma unroll
            for (int j = 0; j < 4; j++) o[i][j] *= alpha;

            *(float4*)&Ps[ty * 4 + i][tx * 4] = make_float4(s[i][0], s[i][1], s[i][2], s[i][3]);
        }
        __syncthreads();

        // Stage 2: O += P @ V
#pragma unroll
        for (int k = 0; k < 64; k += 4) {
            float4 pa[4], vb[4];
#pragma unroll
            for (int i = 0; i < 4; i++) pa[i] = *(const float4*)&Ps[ty * 4 + i][k];
#pragma unroll
            for (int kk = 0; kk < 4; kk++) vb[kk] = *(const float4*)&Vs[k + kk][tx * 4];
#pragma unroll
            for (int i = 0; i < 4; i++) {
                const float* pp = (const float*)&pa[i];
#pragma unroll
                for (int j = 0; j < 4; j++) {
                    float acc = o[i][j];
                    acc = fmaf(pp[0], ((const float*)&vb[0])[j], acc);
                    acc = fmaf(pp[1], ((const float*)&vb[1])[j], acc);
                    acc = fmaf(pp[2], ((const float*)&vb[2])[j], acc);
                    acc = fmaf(pp[3], ((const float*)&vb[3])[j], acc);
                    o[i][j] = acc;
                }
            }
        }
    }

    // Epilogue: normalize and write y[b, q0+r, h, d]
    float* Yg = g_y + ((size_t)(b * Tlen + q0)) * Cdim + h * D;
#pragma unroll
    for (int i = 0; i < 4; i++) {
        const float inv = 1.0f / l_i[i];
        *(float4*)(Yg + (size_t)(ty * 4 + i) * Cdim + tx * 4) =
            make_float4(o[i][0] * inv, o[i][1] * inv, o[i][2] * inv, o[i][3] * inv);
    }
}

// ---------------------------------------------------------------------------
extern "C" void kernel_launch(void* const* d_in, const int* in_sizes, int n_in,
                              void* d_out, int out_size)
{
    const float* x     = (const float*)d_in[0];
    const float* wq    = (const float*)d_in[1];
    const float* wk    = (const float*)d_in[2];
    const float* wv    = (const float*)d_in[3];
    const float* wproj = (const float*)d_in[4];
    float* out = (float*)d_out;

    const int attn_smem = 4 * 64 * 68 * (int)sizeof(float);  // 69632 B
    cudaFuncSetAttribute(attn_kernel, cudaFuncAttributeMaxDynamicSharedMemorySize, attn_smem);

    // 1. q,k,v = x @ W^T
    qkv_gemm_kernel<<<dim3(8, 32, 3), 256>>>(x, wq, wk, wv);

    // 2. RMSNorm + RoPE in-place on q,k  (2 * 4096 * 16 head vectors, warp each)
    rope_kernel<<<(2 * M * H) / 8, 256>>>();

    // 3. causal flash attention -> g_y (heavy q-blocks first)
    attn_kernel<<<dim3(Tlen / 64, Bsz * H), 256, attn_smem>>>();

    // 4. out = y @ w_proj^T
    proj_gemm_kernel<<<dim3(8, 32), 256>>>(wproj, out);
}

// round 17
// speedup vs baseline: 1.3511x; 1.3511x over previous
#include <cuda_runtime.h>
#include <cuda_bf16.h>
#include <math.h>
#include <stdint.h>

// Problem constants
static constexpr int Bsz  = 2;
static constexpr int Tlen = 2048;
static constexpr int Cdim = 1024;
static constexpr int H    = 16;
static constexpr int Dh   = 64;
static constexpr int M    = Bsz * Tlen;       // 4096 rows
static constexpr float RMS_EPS = 1.1920928955078125e-07f;

// Scratch (no allocation allowed)
__device__ float g_q[M * Cdim];
__device__ float g_k[M * Cdim];
__device__ float g_v[M * Cdim];
__device__ float g_y[M * Cdim];
// Pre-split bf16 hi/lo, packed as bf16x2 (k-major pairs): [row][k/2]
__device__ uint32_t g_xh[M * Cdim / 2], g_xl[M * Cdim / 2];            // 8+8 MB
__device__ uint32_t g_wh4[4][Cdim * Cdim / 2], g_wl4[4][Cdim * Cdim / 2]; // 8+8 MB
__device__ uint32_t g_yh[M * Cdim / 2], g_yl[M * Cdim / 2];            // 8+8 MB

// ===========================================================================
// Helpers: standard PTX (sm_80+) tensor-core path. NO tcgen05 — the harness
// assembles for plain sm_103 and all 'a'-suffix features are rejected.
// ===========================================================================
__device__ __forceinline__ uint32_t smem_addr_u32(const void* p) {
    uint32_t a;
    asm("{ .reg .u64 t; cvta.to.shared.u64 t, %1; cvt.u32.u64 %0, t; }"
        : "=r"(a) : "l"(p));
    return a;
}

__device__ __forceinline__ void ldsm_x4(uint32_t& r0, uint32_t& r1,
                                        uint32_t& r2, uint32_t& r3, uint32_t addr) {
    asm volatile("ldmatrix.sync.aligned.m8n8.x4.shared.b16 {%0,%1,%2,%3}, [%4];"
                 : "=r"(r0), "=r"(r1), "=r"(r2), "=r"(r3) : "r"(addr));
}

__device__ __forceinline__ void mma_16816(float* c, const uint32_t* a,
                                          uint32_t b0, uint32_t b1) {
    asm volatile(
        "mma.sync.aligned.m16n8k16.row.col.f32.bf16.bf16.f32 "
        "{%0,%1,%2,%3}, {%4,%5,%6,%7}, {%8,%9}, {%0,%1,%2,%3};"
        : "+f"(c[0]), "+f"(c[1]), "+f"(c[2]), "+f"(c[3])
        : "r"(a[0]), "r"(a[1]), "r"(a[2]), "r"(a[3]), "r"(b0), "r"(b1));
}

// pack two fp32 into bf16x2 (lo elem in low half — matches memory order)
__device__ __forceinline__ uint32_t pack_bf16x2(float lo, float hi) {
    uint32_t r;
    asm("cvt.rn.bf16x2.f32 %0, %1, %2;" : "=r"(r) : "f"(hi), "f"(lo));
    return r;
}

#define SW128(x) ((x) ^ (((x) >> 3) & 0x70))

// ===========================================================================
// Split kernels: fp32 -> packed bf16x2 hi/lo. One float4 -> uint2 hi + uint2 lo.
// ===========================================================================
__device__ __forceinline__ void split4(float4 v, uint2& hv, uint2& lv) {
    uint32_t h0 = pack_bf16x2(v.x, v.y);
    uint32_t h1 = pack_bf16x2(v.z, v.w);
    float l0 = v.x - __uint_as_float(h0 << 16);
    float l1 = v.y - __uint_as_float(h0 & 0xffff0000u);
    float l2 = v.z - __uint_as_float(h1 << 16);
    float l3 = v.w - __uint_as_float(h1 & 0xffff0000u);
    hv = make_uint2(h0, h1);
    lv = make_uint2(pack_bf16x2(l0, l1), pack_bf16x2(l2, l3));
}

// which: 0 = x -> g_xh/g_xl ; 1..4 = weight -> g_wh4/g_wl4[which-1]
__global__ void __launch_bounds__(256) split_in_kernel(const float* __restrict__ src,
                                                       int which) {
    const int i = blockIdx.x * blockDim.x + threadIdx.x;   // float4 index
    uint32_t* hi = (which == 0) ? g_xh : g_wh4[which - 1];
    uint32_t* lo = (which == 0) ? g_xl : g_wl4[which - 1];
    uint2 hv, lv;
    split4(((const float4*)src)[i], hv, lv);
    ((uint2*)hi)[i] = hv;
    ((uint2*)lo)[i] = lv;
}

__global__ void __launch_bounds__(256) split_y_kernel() {
    const int i = blockIdx.x * blockDim.x + threadIdx.x;
    uint2 hv, lv;
    split4(((const float4*)g_y)[i], hv, lv);
    ((uint2*)g_yh)[i] = hv;
    ((uint2*)g_yl)[i] = lv;
}

// ===========================================================================
// Tensor-core GEMM via mma.sync: Cout 128x128 tile per CTA,
// Cout = A[128,1024] @ W[1024,1024]^T, inputs pre-split into bf16 hi/lo:
// D = Ah*Bh + Ah*Bl + Al*Bh (fp32 register accumulators).
// K marched in 16 chunks of 64. Per chunk: all 256 threads COPY packed hi/lo
// tiles into SW128-swizzled smem (no arithmetic), barrier, 8 warps run
// ldmatrix + mma.sync, barrier. Warp tile 32(m) x 64(n): 2x8 m16n8k16 atoms.
// __launch_bounds__(256,2) pins 2 CTAs/SM so copy/mma phases overlap.
// ===========================================================================
static constexpr int GOFF_AH   = 0;
static constexpr int GOFF_AL   = 16384;
static constexpr int GOFF_BH   = 32768;
static constexpr int GOFF_BL   = 49152;
static constexpr int GEMM_SMEM = 65536;

__device__ __forceinline__ void gemm_mma_body(const uint32_t* __restrict__ Ah,
                                              const uint32_t* __restrict__ Al,
                                              const uint32_t* __restrict__ Bh,
                                              const uint32_t* __restrict__ Bl,
                                              float* __restrict__ Cout)
{
    extern __shared__ char gsm[];
    const uint32_t sb  = smem_addr_u32(gsm);
    const int tid  = threadIdx.x;
    const int wid  = tid >> 5;
    const int lane = tid & 31;
    const int m0   = blockIdx.y * 128;
    const int n0   = blockIdx.x * 128;

    const int wm = (wid & 3) * 32;   // warp m offset within tile (4 warps)
    const int wn = (wid >> 2) * 64;  // warp n offset within tile (2 warps)

    float acc[2][8][4];
#pragma unroll
    for (int mi = 0; mi < 2; mi++)
#pragma unroll
        for (int ni = 0; ni < 8; ni++)
#pragma unroll
            for (int j = 0; j < 4; j++) acc[mi][ni][j] = 0.0f;

    // per-lane ldmatrix address components (row within 16, k-block select)
    const int lrow = lane & 15;       // fragment row
    const int lkb  = lane >> 4;       // 0: k-lo 16B block, 1: k-hi

    for (int c = 0; c < 16; c++) {
        // Copy pre-split 128x64 bf16 hi/lo tiles into swizzled smem.
        // Packed row stride = 512 uint32; chunk c starts at uint32 col c*32.
        const uint32_t* Ahp = Ah + (size_t)m0 * 512 + c * 32;
        const uint32_t* Alp = Al + (size_t)m0 * 512 + c * 32;
        const uint32_t* Bhp = Bh + (size_t)n0 * 512 + c * 32;
        const uint32_t* Blp = Bl + (size_t)n0 * 512 + c * 32;
#pragma unroll
        for (int i = 0; i < 8; i++) {
            const int idx = tid + i * 256;
            const int row = idx >> 4;
            const int c4  = idx & 15;
            const uint32_t soff = SW128((uint32_t)(row * 128 + c4 * 8));
            const uint32_t off  = (uint32_t)row * 512 + c4 * 2;
            *(uint2*)(gsm + GOFF_AH + soff) = *(const uint2*)(Ahp + off);
            *(uint2*)(gsm + GOFF_AL + soff) = *(const uint2*)(Alp + off);
            *(uint2*)(gsm + GOFF_BH + soff) = *(const uint2*)(Bhp + off);
            *(uint2*)(gsm + GOFF_BL + soff) = *(const uint2*)(Blp + off);
        }
        __syncthreads();

        // 4 k-steps of 16 per chunk  (audited mma machinery — unchanged)
#pragma unroll
        for (int ks = 0; ks < 4; ks++) {
            const uint32_t kb16 = (uint32_t)((ks * 2 + lkb) * 16);

            // A fragments: 2 m-atoms, hi+lo
            uint32_t ah[2][4], al[2][4];
#pragma unroll
            for (int mi = 0; mi < 2; mi++) {
                const uint32_t aoff = SW128((uint32_t)((wm + mi * 16 + lrow) * 128) + kb16);
                ldsm_x4(ah[mi][0], ah[mi][1], ah[mi][2], ah[mi][3], sb + GOFF_AH + aoff);
                ldsm_x4(al[mi][0], al[mi][1], al[mi][2], al[mi][3], sb + GOFF_AL + aoff);
            }

            // B: 4 pairs of n-atoms (each ldmatrix.x4 covers 16 n rows x 16 k)
#pragma unroll
            for (int p = 0; p < 4; p++) {
                const uint32_t boff = SW128((uint32_t)((wn + p * 16 + lrow) * 128) + kb16);
                uint32_t bh[4], bl[4];
                ldsm_x4(bh[0], bh[1], bh[2], bh[3], sb + GOFF_BH + boff);
                ldsm_x4(bl[0], bl[1], bl[2], bl[3], sb + GOFF_BL + boff);
                // n-atom 2p  : rows wn+p*16+0..7  -> b regs {x[0], x[2]}
                // n-atom 2p+1: rows wn+p*16+8..15 -> b regs {x[1], x[3]}
#pragma unroll
                for (int mi = 0; mi < 2; mi++) {
                    mma_16816(acc[mi][2 * p + 0], ah[mi], bh[0], bh[2]);
                    mma_16816(acc[mi][2 * p + 0], ah[mi], bl[0], bl[2]);
                    mma_16816(acc[mi][2 * p + 0], al[mi], bh[0], bh[2]);
                    mma_16816(acc[mi][2 * p + 1], ah[mi], bh[1], bh[3]);
                    mma_16816(acc[mi][2 * p + 1], ah[mi], bl[1], bl[3]);
                    mma_16816(acc[mi][2 * p + 1], al[mi], bh[1], bh[3]);
                }
            }
        }
        __syncthreads();   // smem consumed; safe to overwrite next chunk
    }

    // Epilogue: fragment layout c0,c1 -> (row t/4, col (t%4)*2), c2,c3 -> row+8
    const int frow = lane >> 2;
    const int fcol = (lane & 3) * 2;
#pragma unroll
    for (int mi = 0; mi < 2; mi++) {
#pragma unroll
        for (int ni = 0; ni < 8; ni++) {
            const int gr = m0 + wm + mi * 16 + frow;
            const int gc = n0 + wn + ni * 8 + fcol;
            *(float2*)(Cout + (size_t)gr * 1024 + gc) =
                make_float2(acc[mi][ni][0], acc[mi][ni][1]);
            *(float2*)(Cout + (size_t)(gr + 8) * 1024 + gc) =
                make_float2(acc[mi][ni][2], acc[mi][ni][3]);
        }
    }
}

__global__ void __launch_bounds__(256, 2) qkv_gemm_mma()
{
    const int z = blockIdx.z;
    float* out = (z == 0) ? g_q : (z == 1) ? g_k : g_v;
    gemm_mma_body(g_xh, g_xl, g_wh4[z], g_wl4[z], out);
}

__global__ void __launch_bounds__(256, 2) proj_gemm_mma(float* __restrict__ out)
{
    gemm_mma_body(g_yh, g_yl, g_wh4[3], g_wl4[3], out);
}

// ---------------------------------------------------------------------------
// RMSNorm + RoPE, in-place on g_q and g_k. One warp per (b,t,h) head vector.
// ---------------------------------------------------------------------------
__global__ void __launch_bounds__(256) rope_kernel()
{
    const int warp = blockIdx.x * 8 + (threadIdx.x >> 5);
    const int lane = threadIdx.x & 31;
    const int NV   = M * H;

    float* buf = (warp < NV) ? g_q : g_k;
    const int v = (warp < NV) ? warp : warp - NV;

    const int row = v >> 4;
    const int h   = v & 15;
    const int t   = row & (Tlen - 1);

    float* p = buf + (size_t)row * Cdim + h * Dh;
    float x1 = p[lane];
    float x2 = p[lane + 32];

    float ss = x1 * x1 + x2 * x2;
#pragma unroll
    for (int m = 16; m > 0; m >>= 1)
        ss += __shfl_xor_sync(0xffffffffu, ss, m);

    const float r = rsqrtf(ss * (1.0f / 64.0f) + RMS_EPS);

    const float LOG2_BASE_OVER_32 = 0.41524101186092029f;  // log2(10000)/32
    const float inv_freq = exp2f(-(float)lane * LOG2_BASE_OVER_32);
    const float ang = (float)t * inv_freq;
    float s, c;
    sincosf(ang, &s, &c);   // accurate: angles reach ~2048 rad

    const float n1 = x1 * r;
    const float n2 = x2 * r;
    p[lane]      = n1 * c + n2 * s;
    p[lane + 32] = n2 * c - n1 * s;
}

// ---------------------------------------------------------------------------
// Causal flash attention, fp32 (unchanged from passing round-4 kernel).
// ---------------------------------------------------------------------------
__global__ void __launch_bounds__(256, 2) attn_kernel()
{
    extern __shared__ float sm[];
    float (*Qs)[68]  = (float(*)[68])(sm);
    float (*Kst)[68] = (float(*)[68])(sm + 64 * 68);
    float (*Vs)[68]  = (float(*)[68])(sm + 2 * 64 * 68);
    float (*Ps)[68]  = (float(*)[68])(sm + 3 * 64 * 68);

    const int tid = threadIdx.x;
    const int tx  = tid & 15;
    const int ty  = tid >> 4;
    const int qb  = (gridDim.x - 1 - blockIdx.x);   // heavy blocks first
    const int q0  = qb * 64;
    const int bh  = blockIdx.y;
    const int b   = bh >> 4;
    const int h   = bh & 15;

    const float* Qg = g_q + ((size_t)(b * Tlen + q0)) * Cdim + h * Dh;

    {
        const int r  = tid >> 2;
        const int dc = (tid & 3) * 16;
#pragma unroll
        for (int i = 0; i < 4; i++) {
            float4 qv = *(const float4*)(Qg + (size_t)r * Cdim + dc + 4 * i);
            *(float4*)&Qs[r][dc + 4 * i] = qv;
        }
    }

    float m_i[4], l_i[4], o[4][4];
#pragma unroll
    for (int i = 0; i < 4; i++) {
        m_i[i] = -INFINITY;
        l_i[i] = 0.0f;
#pragma unroll
        for (int j = 0; j < 4; j++) o[i][j] = 0.0f;
    }
    __syncthreads();

    const int ntiles = qb + 1;
    const float scale = 0.125f;

    for (int kt = 0; kt < ntiles; kt++) {
        const int k0 = kt * 64;
        __syncthreads();

        {
            const float* Kg = g_k + ((size_t)(b * Tlen + k0)) * Cdim + h * Dh;
            const float* Vg = g_v + ((size_t)(b * Tlen + k0)) * Cdim + h * Dh;
            const int c  = tid >> 4;
            const int dd = (tid & 15) * 4;
#pragma unroll
            for (int ii = 0; ii < 4; ii++) {
                const int cc = c + ii * 16;
                float4 kv = *(const float4*)(Kg + (size_t)cc * Cdim + dd);
                Kst[dd + 0][cc] = kv.x; Kst[dd + 1][cc] = kv.y;
                Kst[dd + 2][cc] = kv.z; Kst[dd + 3][cc] = kv.w;
                float4 vv = *(const float4*)(Vg + (size_t)cc * Cdim + dd);
                *(float4*)&Vs[cc][dd] = vv;
            }
        }
        __syncthreads();

        float s[4][4];
#pragma unroll
        for (int i = 0; i < 4; i++)
#pragma unroll
            for (int j = 0; j < 4; j++) s[i][j] = 0.0f;

#pragma unroll
        for (int d = 0; d < 64; d += 4) {
            float4 qa[4], kb[4];
#pragma unroll
            for (int i = 0; i < 4; i++) qa[i] = *(const float4*)&Qs[ty * 4 + i][d];
#pragma unroll
            for (int dd = 0; dd < 4; dd++) kb[dd] = *(const float4*)&Kst[d + dd][tx * 4];
#pragma unroll
            for (int i = 0; i < 4; i++) {
                const float* qp = (const float*)&qa[i];
#pragma unroll
                for (int j = 0; j < 4; j++) {
                    float acc = s[i][j];
                    acc = fmaf(qp[0], ((const float*)&kb[0])[j], acc);
                    acc = fmaf(qp[1], ((const float*)&kb[1])[j], acc);
                    acc = fmaf(qp[2], ((const float*)&kb[2])[j], acc);
                    acc = fmaf(qp[3], ((const float*)&kb[3])[j], acc);
                    s[i][j] = acc;
                }
            }
        }

        const bool diag = (k0 == q0);
#pragma unroll
        for (int i = 0; i < 4; i++)
#pragma unroll
            for (int j = 0; j < 4; j++) {
                float v = s[i][j] * scale;
                if (diag && (tx * 4 + j > ty * 4 + i)) v = -INFINITY;
                s[i][j] = v;
            }

#pragma unroll
        for (int i = 0; i < 4; i++) {
            float mx = fmaxf(fmaxf(s[i][0], s[i][1]), fmaxf(s[i][2], s[i][3]));
#pragma unroll
            for (int mm = 8; mm > 0; mm >>= 1)
                mx = fmaxf(mx, __shfl_xor_sync(0xffffffffu, mx, mm));
            const float mnew  = fmaxf(m_i[i], mx);
            const float alpha = __expf(m_i[i] - mnew);
            m_i[i] = mnew;

            float rs = 0.0f;
#pragma unroll
            for (int j = 0; j < 4; j++) {
                float p = __expf(s[i][j] - mnew);
                s[i][j] = p;
                rs += p;
            }
#pragma unroll
            for (int mm = 8; mm > 0; mm >>= 1)
                rs += __shfl_xor_sync(0xffffffffu, rs, mm);

            l_i[i] = l_i[i] * alpha + rs;
#pragma unroll
            for (int j = 0; j < 4; j++) o[i][j] *= alpha;

            *(float4*)&Ps[ty * 4 + i][tx * 4] = make_float4(s[i][0], s[i][1], s[i][2], s[i][3]);
        }
        __syncthreads();

#pragma unroll
        for (int k = 0; k < 64; k += 4) {
            float4 pa[4], vb[4];
#pragma unroll
            for (int i = 0; i < 4; i++) pa[i] = *(const float4*)&Ps[ty * 4 + i][k];
#pragma unroll
            for (int kk = 0; kk < 4; kk++) vb[kk] = *(const float4*)&Vs[k + kk][tx * 4];
#pragma unroll
            for (int i = 0; i < 4; i++) {
                const float* pp = (const float*)&pa[i];
#pragma unroll
                for (int j = 0; j < 4; j++) {
                    float acc = o[i][j];
                    acc = fmaf(pp[0], ((const float*)&vb[0])[j], acc);
                    acc = fmaf(pp[1], ((const float*)&vb[1])[j], acc);
                    acc = fmaf(pp[2], ((const float*)&vb[2])[j], acc);
                    acc = fmaf(pp[3], ((const float*)&vb[3])[j], acc);
                    o[i][j] = acc;
                }
            }
        }
    }

    float* Yg = g_y + ((size_t)(b * Tlen + q0)) * Cdim + h * Dh;
#pragma unroll
    for (int i = 0; i < 4; i++) {
        const float inv = 1.0f / l_i[i];
        *(float4*)(Yg + (size_t)(ty * 4 + i) * Cdim + tx * 4) =
            make_float4(o[i][0] * inv, o[i][1] * inv, o[i][2] * inv, o[i][3] * inv);
    }
}

// ---------------------------------------------------------------------------
extern "C" void kernel_launch(void* const* d_in, const int* in_sizes, int n_in,
                              void* d_out, int out_size)
{
    const float* x     = (const float*)d_in[0];
    const float* wq    = (const float*)d_in[1];
    const float* wk    = (const float*)d_in[2];
    const float* wv    = (const float*)d_in[3];
    const float* wproj = (const float*)d_in[4];
    float* out = (float*)d_out;

    const int attn_smem = 4 * 64 * 68 * (int)sizeof(float);  // 69632 B
    cudaFuncSetAttribute(attn_kernel, cudaFuncAttributeMaxDynamicSharedMemorySize, attn_smem);
    cudaFuncSetAttribute(qkv_gemm_mma, cudaFuncAttributeMaxDynamicSharedMemorySize, GEMM_SMEM);
    cudaFuncSetAttribute(proj_gemm_mma, cudaFuncAttributeMaxDynamicSharedMemorySize, GEMM_SMEM);

    // 0. one-time bf16 hi/lo pre-split of x and all weights
    split_in_kernel<<<4096, 256>>>(x, 0);       // 4M elts = 1M float4
    split_in_kernel<<<1024, 256>>>(wq, 1);      // 1M elts = 256K float4
    split_in_kernel<<<1024, 256>>>(wk, 2);
    split_in_kernel<<<1024, 256>>>(wv, 3);
    split_in_kernel<<<1024, 256>>>(wproj, 4);

    // 1. q,k,v = x @ W^T  (mma.sync bf16-split tensor cores)
    qkv_gemm_mma<<<dim3(8, 32, 3), 256, GEMM_SMEM>>>();

    // 2. RMSNorm + RoPE in-place on q,k
    rope_kernel<<<(2 * M * H) / 8, 256>>>();

    // 3. causal flash attention -> g_y (heavy q-blocks first)
    attn_kernel<<<dim3(Tlen / 64, Bsz * H), 256, attn_smem>>>();

    // 3b. split attention output for the projection GEMM
    split_y_kernel<<<4096, 256>>>();

    // 4. out = y @ w_proj^T  (mma.sync bf16-split tensor cores)
    proj_gemm_mma<<<dim3(8, 32), 256, GEMM_SMEM>>>(out);
}